// round 3
// baseline (speedup 1.0000x reference)
#include <cuda_runtime.h>

// LIF scan, temporally parallelized with exact speculative splicing.
// B=16, S=256, H=128, N=64.  T = S*H = 32768 steps per (b,n) chain.
//
// Key property: on fire, acc resets to exactly 0.0f, erasing history. A
// speculative run started from acc=0 merges BIT-EXACTLY with the true
// trajectory at the first shared fire. We split each chain into 16
// segments of 2048 steps; segments k>0 warm up speculatively for 512
// steps from acc=0. A verify/fixup kernel bit-compares each segment's
// post-warmup state against the previous segment's end state and
// serially recomputes any segment that failed to merge (never happens
// in practice; correctness is unconditional either way).
//
// Step math (bit-identical to reference order, all fma-pipe, no
// predicates on the carried chain):
//     m = (v <= thr) ? 1.0 : 0.0        (FSET)
//     v = fmaf(v, m, x)                  (FFMA; v*1+x == round(v+x), v*0+x == x)
//     g = (v > thr) ? 1.0 : 0.0          (off-chain; g IS the spike value)
//     out = v * g                        (off-chain; exactly v or 0)

#define BB 16
#define SS 256
#define HH 128
#define NN 64
#define TT (SS * HH)

#define NSEG 16
#define ROWS_PER_SEG (SS / NSEG)   // 16 s-rows per segment
#define WARM_ROWS 4                // 512-step speculative warm-up
#define ROWPAD 132                 // conflict-free float4 staging stride
#define NGRP 32                    // (b, neuron-half) groups

static const size_t BSNH = (size_t)BB * SS * NN * HH;  // 33,554,432

// Splice verification state (rewritten every launch; no allocations).
__device__ float g_end [NSEG][NGRP][32];
__device__ float g_spec[NSEG][NGRP][32];

__device__ __forceinline__ float set_le(float a, float b) {
    float r; asm("set.le.f32.f32 %0, %1, %2;" : "=f"(r) : "f"(a), "f"(b)); return r;
}
__device__ __forceinline__ float set_gt(float a, float b) {
    float r; asm("set.gt.f32.f32 %0, %1, %2;" : "=f"(r) : "f"(a), "f"(b)); return r;
}

// One exact LIF step. v carries the post-add value; reset is folded into
// the next step's FFMA via the mask.
#define LIF_STEP(XC, OC) do {                      \
    float _m = set_le(v, thr);                     \
    v = __fmaf_rn(v, _m, (XC));                    \
    float _g = set_gt(v, thr);                     \
    (OC) = v * _g;                                 \
} while (0)

__global__ void __launch_bounds__(64, 1)
lif_seg_kernel(const float* __restrict__ x,       // [B, S, H]
               const float* __restrict__ thresh,  // [N]
               const float* __restrict__ acc0,    // [B, N]
               float* __restrict__ outbuf,        // outs | spikes
               int write_spikes)
{
    __shared__ float sbuf[2][32 * ROWPAD];                       // out staging
    __shared__ float xsh[(WARM_ROWS + ROWS_PER_SEG) * HH + 4];   // x staging (+pad)

    const int tid  = threadIdx.x;
    const int grp  = blockIdx.x & 31;       // (b, half)
    const int seg  = blockIdx.x >> 5;       // temporal segment
    const int b    = grp >> 1;
    const int n0   = (grp & 1) * 32;
    const int warm = (seg == 0) ? 0 : WARM_ROWS;
    const int s0   = seg * ROWS_PER_SEG;
    const int nrows = warm + ROWS_PER_SEG;

    // Cooperative prefetch of this segment's x (incl. warm-up) into smem.
    {
        const float4* xg = (const float4*)(x + (size_t)b * TT + (size_t)(s0 - warm) * HH);
        float4* xs4 = (float4*)xsh;
        const int nch = nrows * (HH / 4);
        for (int i = tid; i < nch; i += 64) xs4[i] = xg[i];
    }
    __syncthreads();

    if (tid < 32) {
        // ------------- producer warp: the carried recurrence -------------
        const int lane = tid;
        const int n    = n0 + lane;
        const float thr = thresh[n];
        float v = (seg == 0) ? acc0[b * NN + n] : 0.0f;  // speculative reset

        const float4* xp = (const float4*)xsh;
        float4 xv = xp[0];
        int c = 0;

        // Speculative warm-up: chain only, outputs discarded.
        for (int w = 0; w < warm * (HH / 4); ++w) {
            float4 xn = xp[c + 1];
            float od;
            LIF_STEP(xv.x, od); LIF_STEP(xv.y, od);
            LIF_STEP(xv.z, od); LIF_STEP(xv.w, od);
            xv = xn; ++c;
        }

        // Record post-reset state entering the real segment (splice check).
        { float m = set_le(v, thr); g_spec[seg][grp][lane] = v * m; }

        float* const row0 = &sbuf[0][lane * ROWPAD];
        float* const row1 = &sbuf[1][lane * ROWPAD];

        for (int r = 0; r < ROWS_PER_SEG; ++r) {
            float* rw = (r & 1) ? row1 : row0;
            #pragma unroll 4
            for (int q = 0; q < HH / 4; ++q) {
                float4 xn = xp[c + 1];    // prefetch next chunk (pad-covered)
                float4 o;
                LIF_STEP(xv.x, o.x); LIF_STEP(xv.y, o.y);
                LIF_STEP(xv.z, o.z); LIF_STEP(xv.w, o.w);
                *(float4*)&rw[q * 4] = o;  // conflict-free STS.128
                xv = xn; ++c;
            }
            __syncthreads();               // row r staged
        }

        // Record post-reset end state.
        { float m = set_le(v, thr); g_end[seg][grp][lane] = v * m; }
    } else {
        // ------------- flusher warp: transpose + spikes ------------------
        const int lane = tid - 32;
        float* __restrict__ outp = outbuf;
        float* __restrict__ spkp = outbuf + BSNH;

        for (int r = 0; r < ROWS_PER_SEG; ++r) {
            __syncthreads();               // wait for row r
            const float* buf = sbuf[r & 1];
            const int s = s0 + r;
            size_t base = (((size_t)b * SS + s) * NN + n0) * HH + lane * 4;
            #pragma unroll 4
            for (int rr = 0; rr < 32; ++rr) {
                float4 vv = *(const float4*)&buf[rr * ROWPAD + lane * 4];
                *(float4*)&outp[base + (size_t)rr * HH] = vv;  // 512B coalesced
                if (write_spikes) {
                    float4 sp;
                    sp.x = (vv.x > 0.0f) ? 1.0f : 0.0f;
                    sp.y = (vv.y > 0.0f) ? 1.0f : 0.0f;
                    sp.z = (vv.z > 0.0f) ? 1.0f : 0.0f;
                    sp.w = (vv.w > 0.0f) ? 1.0f : 0.0f;
                    *(float4*)&spkp[base + (size_t)rr * HH] = sp;
                }
            }
        }
    }
}

// Verify splices; serially recompute any segment whose speculative start
// state does not bit-match the previous segment's end state. Cascades
// corrections left-to-right, so the result is unconditionally exact.
__global__ void lif_fixup(const float* __restrict__ x,
                          const float* __restrict__ thresh,
                          float* __restrict__ outbuf,
                          int write_spikes)
{
    int cidx = blockIdx.x * blockDim.x + threadIdx.x;
    if (cidx >= NGRP * 32) return;
    const int grp = cidx >> 5, lane = cidx & 31;
    const int b = grp >> 1, n = (grp & 1) * 32 + lane;
    const float thr = thresh[n];

    float* __restrict__ outp = outbuf;
    float* __restrict__ spkp = outbuf + BSNH;

    float cur = g_end[0][grp][lane];   // segment 0 starts from true acc0
    for (int k = 1; k < NSEG; ++k) {
        float spec = g_spec[k][grp][lane];
        if (spec != cur) {
            // Failed merge: recompute segment k exactly from `cur`.
            float v = cur;
            for (int r = 0; r < ROWS_PER_SEG; ++r) {
                const int s = k * ROWS_PER_SEG + r;
                const float* xr = x + (size_t)b * TT + (size_t)s * HH;
                size_t base = (((size_t)b * SS + s) * NN + n) * HH;
                for (int h = 0; h < HH; ++h) {
                    float m = set_le(v, thr);
                    v = __fmaf_rn(v, m, xr[h]);
                    float g = set_gt(v, thr);
                    float o = v * g;
                    outp[base + h] = o;
                    if (write_spikes) spkp[base + h] = g;
                }
            }
            float m = set_le(v, thr);
            cur = v * m;
        } else {
            cur = g_end[k][grp][lane];
        }
    }
}

extern "C" void kernel_launch(void* const* d_in, const int* in_sizes, int n_in,
                              void* d_out, int out_size)
{
    const float* x      = (const float*)d_in[0];  // [16, 256, 128] f32
    const float* thresh = (const float*)d_in[1];  // [64] f32
    const float* acc0   = (const float*)d_in[2];  // [16, 64] f32
    float* out = (float*)d_out;

    int write_spikes = ((size_t)out_size >= 2 * BSNH) ? 1 : 0;

    lif_seg_kernel<<<NGRP * NSEG, 64>>>(x, thresh, acc0, out, write_spikes);
    lif_fixup<<<4, 256>>>(x, thresh, out, write_spikes);
}

// round 4
// speedup vs baseline: 12.0591x; 12.0591x over previous
#include <cuda_runtime.h>

// LIF scan, exact two-phase checkpointing.
// B=16, S=256, H=128, N=64.  T = S*H = 32768 steps per (b,n) chain.
//
// Phase 1 (lif_prepass): serial state-only chain per (b,n), minimal
//   critical path (FSET + FFMA = ~8 cyc/step), records the TRUE carried
//   state at every 1024-step block boundary (32 checkpoints per chain).
// Phase 2 (lif_output): 1024 independent CTAs each replay one block from
//   its exact checkpoint, producing outs + spikes with a smem-transpose
//   producer/flusher pair for fully coalesced 512B global stores.
//
// Step math (bit-identical to the reference sequential order):
//   carried v = post-add accumulator value.
//   m = (v <= thr) ? 1.0 : 0.0      (FSET; reset folded into next FFMA)
//   v = fmaf(v, m, x)               (v*1+x == round(v+x); v*0+x == x; exact)
//   g = (v > thr) ? 1.0 : 0.0      (g IS the spike value)
//   out = v * g                     (exactly v when fired, else +/-0)

#define BB 16
#define SS 256
#define HH 128
#define NN 64
#define TT (SS * HH)

#define BLKROWS 8              // s-rows per output block (1024 steps)
#define NBLK (SS / BLKROWS)    // 32 checkpoints per chain
#define ROWPAD 132             // conflict-free float4 staging stride

static const size_t BSNH = (size_t)BB * SS * NN * HH;  // 33,554,432

// True chain states at block boundaries (raw carried v).
__device__ float g_chk[NBLK][BB][NN];

__device__ __forceinline__ float set_le(float a, float b) {
    float r; asm("set.le.f32.f32 %0, %1, %2;" : "=f"(r) : "f"(a), "f"(b)); return r;
}
__device__ __forceinline__ float set_gt(float a, float b) {
    float r; asm("set.gt.f32.f32 %0, %1, %2;" : "=f"(r) : "f"(a), "f"(b)); return r;
}

#define CHAIN_STEP(XC) do {                 \
    float _m = set_le(v, thr);              \
    v = __fmaf_rn(v, _m, (XC));             \
} while (0)

#define OUT_STEP(XC, OC) do {               \
    float _m = set_le(v, thr);              \
    v = __fmaf_rn(v, _m, (XC));             \
    float _g = set_gt(v, thr);              \
    (OC) = v * _g;                          \
} while (0)

// ---------------------------------------------------------------------------
// Phase 1: serial state chain, checkpoint every BLKROWS s-rows.
// grid = 16 (one CTA per batch), block = 64 (lane = neuron).
// ---------------------------------------------------------------------------
__global__ void __launch_bounds__(64, 1)
lif_prepass(const float* __restrict__ x,       // [B, S, H]
            const float* __restrict__ thresh,  // [N]
            const float* __restrict__ acc0)    // [B, N]
{
    const int b = blockIdx.x;
    const int n = threadIdx.x;
    const float thr = thresh[n];
    float v = acc0[b * NN + n];

    const float4* __restrict__ xp = (const float4*)(x + (size_t)b * TT);
    int c = 0;

    for (int blk = 0; blk < NBLK; ++blk) {
        g_chk[blk][b][n] = v;     // raw carried state entering this block
        #pragma unroll 8
        for (int q = 0; q < BLKROWS * (HH / 4); ++q) {
            float4 xv = xp[c + q];           // broadcast LDG.128, off-chain
            CHAIN_STEP(xv.x); CHAIN_STEP(xv.y);
            CHAIN_STEP(xv.z); CHAIN_STEP(xv.w);
        }
        c += BLKROWS * (HH / 4);
    }
}

// ---------------------------------------------------------------------------
// Phase 2: parallel block replay with coalesced output.
// grid = B * 2 * NBLK = 1024, block = 64 (warp0 producer, warp1 flusher).
// ---------------------------------------------------------------------------
__global__ void __launch_bounds__(64, 1)
lif_output(const float* __restrict__ x,
           const float* __restrict__ thresh,
           float* __restrict__ outbuf,
           int write_spikes)
{
    __shared__ float sbuf[2][32 * ROWPAD];

    const int tid  = threadIdx.x;
    const int sblk = blockIdx.x & (NBLK - 1);        // which s-block
    const int half = (blockIdx.x >> 5) & 1;          // neuron half
    const int b    = blockIdx.x >> 6;                // batch
    const int n0   = half * 32;
    const int s0   = sblk * BLKROWS;

    if (tid < 32) {
        // ---------------- producer: exact replay from checkpoint ---------
        const int lane = tid;
        const int n    = n0 + lane;
        const float thr = thresh[n];
        float v = g_chk[sblk][b][n];

        const float4* __restrict__ xp =
            (const float4*)(x + (size_t)b * TT + (size_t)s0 * HH);

        float* const row0 = &sbuf[0][lane * ROWPAD];
        float* const row1 = &sbuf[1][lane * ROWPAD];

        for (int r = 0; r < BLKROWS; ++r) {
            float* rw = (r & 1) ? row1 : row0;
            const float4* xrow = xp + r * (HH / 4);
            #pragma unroll 8
            for (int q = 0; q < HH / 4; ++q) {
                float4 xv = xrow[q];         // broadcast LDG.128
                float4 o;
                OUT_STEP(xv.x, o.x); OUT_STEP(xv.y, o.y);
                OUT_STEP(xv.z, o.z); OUT_STEP(xv.w, o.w);
                *(float4*)&rw[q * 4] = o;    // conflict-free STS.128
            }
            __syncthreads();                 // row r staged
        }
    } else {
        // ---------------- flusher: transpose + spikes --------------------
        const int lane = tid - 32;
        float* __restrict__ outp = outbuf;
        float* __restrict__ spkp = outbuf + BSNH;

        for (int r = 0; r < BLKROWS; ++r) {
            __syncthreads();                 // wait for row r
            const float* buf = sbuf[r & 1];
            const int s = s0 + r;
            size_t base = (((size_t)b * SS + s) * NN + n0) * HH + lane * 4;
            #pragma unroll 4
            for (int rr = 0; rr < 32; ++rr) {
                float4 vv = *(const float4*)&buf[rr * ROWPAD + lane * 4];
                *(float4*)&outp[base + (size_t)rr * HH] = vv;  // 512B coalesced
                if (write_spikes) {
                    float4 sp;
                    sp.x = (vv.x > 0.0f) ? 1.0f : 0.0f;
                    sp.y = (vv.y > 0.0f) ? 1.0f : 0.0f;
                    sp.z = (vv.z > 0.0f) ? 1.0f : 0.0f;
                    sp.w = (vv.w > 0.0f) ? 1.0f : 0.0f;
                    *(float4*)&spkp[base + (size_t)rr * HH] = sp;
                }
            }
        }
    }
}

extern "C" void kernel_launch(void* const* d_in, const int* in_sizes, int n_in,
                              void* d_out, int out_size)
{
    const float* x      = (const float*)d_in[0];  // [16, 256, 128] f32
    const float* thresh = (const float*)d_in[1];  // [64] f32
    const float* acc0   = (const float*)d_in[2];  // [16, 64] f32
    float* out = (float*)d_out;

    int write_spikes = ((size_t)out_size >= 2 * BSNH) ? 1 : 0;

    lif_prepass<<<BB, NN>>>(x, thresh, acc0);
    lif_output<<<BB * 2 * NBLK, 64>>>(x, thresh, out, write_spikes);
}